// round 4
// baseline (speedup 1.0000x reference)
#include <cuda_runtime.h>
#include <math.h>
#include <stdint.h>

#define BATCH 4
#define SEQ   1024
#define HID   768
#define HEADS 12
#define NENT  32
#define MENT  4
#define WD    768
#define AD    256
#define NC    97
#define SPLITK 64
#define DD    12
#define PP    144          // DD*DD
#define NPAIR (NENT*NENT)  // 1024

// ---------------- device scratch ----------------
__device__ float d_rep[BATCH*NENT*HID];
__device__ float d_rso[BATCH*NENT*2*WD];          // [128][1536] : rs | ro
__device__ float d_Wso[WD*2*WD];                  // [768][1536] : W_s | W_o
__device__ float d_ga [BATCH*NENT*HEADS*SEQ];
__device__ float d_pa [(size_t)BATCH*NPAIR*SEQ];
__device__ float d_ctxh[(size_t)BATCH*NPAIR*HID];
__device__ float d_Zs [(size_t)BATCH*NPAIR*WD];
__device__ float d_Zo [(size_t)BATCH*NPAIR*WD];
__device__ float d_P  [(size_t)BATCH*NPAIR*PP];
__device__ float d_g  [(size_t)BATCH*NPAIR*WD];
__device__ float d_t  [(size_t)BATCH*NPAIR*AD];
__device__ float d_e  [BATCH*NPAIR];
__device__ float d_arow[BATCH*NPAIR];
__device__ float d_acol[BATCH*NPAIR];
__device__ float d_Ablt[PP*WD];
__device__ float d_gclf[(size_t)BATCH*NPAIR*NC];
__device__ float d_rgcg[2*BATCH*NENT*NC];
__device__ float d_part[1700000];                 // split-K partials

// ---------------- tf32 helpers ----------------
__device__ __forceinline__ uint32_t f2tf32(float x)
{
    uint32_t r;
    asm("cvt.rna.tf32.f32 %0, %1;" : "=r"(r) : "f"(x));
    return r;
}

__device__ __forceinline__ void mma_tf32(float* c, const uint32_t* a, const uint32_t* b)
{
    asm volatile(
        "mma.sync.aligned.m16n8k8.row.col.f32.tf32.tf32.f32 "
        "{%0,%1,%2,%3}, {%4,%5,%6,%7}, {%8,%9}, {%0,%1,%2,%3};"
        : "+f"(c[0]), "+f"(c[1]), "+f"(c[2]), "+f"(c[3])
        : "r"(a[0]), "r"(a[1]), "r"(a[2]), "r"(a[3]), "r"(b[0]), "r"(b[1]));
}

// ---------------- pipelined tf32 tensor-core GEMM ----------------
// C[M,N] = A[M,K] row * B[K,N] row.  BM=128, BN=16*NT, BK=16, 256 thr = 8 warps
// (4 m-warps x 2 n-warps), warp tile 32 x (8*NT). Fragment-order smem, tf32
// convert at store. Ping-pong smem + register staging: one sync/iter, gmem
// latency overlapped with MMA compute.
// MODE 0: C = acc (+ biasScale*bias[n] if bias).
// MODE 1: C = tanh(acc + bias[(gm>>5)*biasStride+gn]); C2 likewise with bias2.
// Requirements: M%128==0, (K/kSplit)%16==0.
template<int NT, int MODE>
__global__ __launch_bounds__(256)
void mma_gemm(const float* __restrict__ A, const float* __restrict__ B,
              float* __restrict__ C, float* __restrict__ C2,
              int M, int N, int K,
              long long sA, long long sB, long long sC,
              int kSplit, long long partStride,
              const float* __restrict__ bias, float biasScale,
              const float* __restrict__ bias2, int biasStride)
{
    const int BN = 16 * NT;
    const int NTILES = 2 * NT;          // 8-col n-tiles per k8 slice
    const int NB = (NT + 3) / 4;        // B float4 loads per thread
    __shared__ uint32_t As[2][2 * 8 * 32 * 4];
    __shared__ uint32_t Bs[2][2 * NTILES * 32 * 2];

    int zb = blockIdx.z / kSplit;
    int kz = blockIdx.z - zb * kSplit;
    A += (long long)zb * sA;
    B += (long long)zb * sB;
    C += (long long)zb * sC + (long long)kz * partStride;

    int row0 = blockIdx.y * 128;
    int col0 = blockIdx.x * BN;
    int tid = threadIdx.x, lane = tid & 31, w = tid >> 5;
    int wm = w & 3, wn = w >> 2;
    int groupID = lane >> 2, tig = lane & 3;

    int kLen = K / kSplit;
    int k0beg = kz * kLen, k0end = k0beg + kLen;

    float acc[2][NT][4];
    #pragma unroll
    for (int i = 0; i < 2; i++)
        #pragma unroll
        for (int j = 0; j < NT; j++)
            #pragma unroll
            for (int r = 0; r < 4; r++) acc[i][j][r] = 0.f;

    const bool nvec = ((N & 3) == 0);

    float4 va[2], vb[NB];

    // ---- prefetch first tiles ----
    {
        int kk = k0beg;
        #pragma unroll
        for (int i = 0; i < 2; i++) {
            int l = tid + i * 256;
            int m = l >> 2, kq = l & 3;
            va[i] = *(const float4*)(A + (long long)(row0 + m) * K + kk + kq * 4);
        }
        #pragma unroll
        for (int nb = 0; nb < NB; nb++) {
            int l = tid + nb * 256;
            int kl = l / (BN / 4), nq = l % (BN / 4);
            if (nvec) {
                vb[nb] = *(const float4*)(B + (long long)(kk + kl) * N + col0 + nq * 4);
            } else {
                const float* bp = B + (long long)(kk + kl) * N;
                int n0 = col0 + nq * 4;
                vb[nb].x = (n0 + 0 < N) ? bp[n0 + 0] : 0.f;
                vb[nb].y = (n0 + 1 < N) ? bp[n0 + 1] : 0.f;
                vb[nb].z = (n0 + 2 < N) ? bp[n0 + 2] : 0.f;
                vb[nb].w = (n0 + 3 < N) ? bp[n0 + 3] : 0.f;
            }
        }
    }

    int buf = 0;
    for (int k0 = k0beg; k0 < k0end; k0 += 16) {
        // ---- store staged tiles to smem (tf32, fragment order) ----
        #pragma unroll
        for (int i = 0; i < 2; i++) {
            int l = tid + i * 256;
            int m = l >> 2, kq = l & 3;
            int mt = m >> 4, row = m & 15;
            int k8 = kq >> 1;
            int reg = (row >> 3) + ((kq & 1) << 1);
            int base = (((k8 * 8 + mt) * 32) + (row & 7) * 4) * 4 + reg;
            As[buf][base + 0]  = f2tf32(va[i].x);
            As[buf][base + 4]  = f2tf32(va[i].y);
            As[buf][base + 8]  = f2tf32(va[i].z);
            As[buf][base + 12] = f2tf32(va[i].w);
        }
        #pragma unroll
        for (int nb = 0; nb < NB; nb++) {
            int l = tid + nb * 256;
            int kl = l / (BN / 4), nq = l % (BN / 4);
            int k8 = kl >> 3;
            int reg = (kl >> 2) & 1;
            int ktig = kl & 3;
            int nt = (nq * 4) >> 3;
            int gbase = (nq * 4) & 7;
            int base = (((k8 * NTILES + nt) * 32) + gbase * 4 + ktig) * 2 + reg;
            Bs[buf][base + 0]  = f2tf32(vb[nb].x);
            Bs[buf][base + 8]  = f2tf32(vb[nb].y);
            Bs[buf][base + 16] = f2tf32(vb[nb].z);
            Bs[buf][base + 24] = f2tf32(vb[nb].w);
        }
        __syncthreads();

        // ---- prefetch next iteration while computing this one ----
        int kn = k0 + 16;
        if (kn < k0end) {
            #pragma unroll
            for (int i = 0; i < 2; i++) {
                int l = tid + i * 256;
                int m = l >> 2, kq = l & 3;
                va[i] = *(const float4*)(A + (long long)(row0 + m) * K + kn + kq * 4);
            }
            #pragma unroll
            for (int nb = 0; nb < NB; nb++) {
                int l = tid + nb * 256;
                int kl = l / (BN / 4), nq = l % (BN / 4);
                if (nvec) {
                    vb[nb] = *(const float4*)(B + (long long)(kn + kl) * N + col0 + nq * 4);
                } else {
                    const float* bp = B + (long long)(kn + kl) * N;
                    int n0 = col0 + nq * 4;
                    vb[nb].x = (n0 + 0 < N) ? bp[n0 + 0] : 0.f;
                    vb[nb].y = (n0 + 1 < N) ? bp[n0 + 1] : 0.f;
                    vb[nb].z = (n0 + 2 < N) ? bp[n0 + 2] : 0.f;
                    vb[nb].w = (n0 + 3 < N) ? bp[n0 + 3] : 0.f;
                }
            }
        }

        // ---- compute ----
        #pragma unroll
        for (int k8 = 0; k8 < 2; k8++) {
            uint32_t a[2][4];
            #pragma unroll
            for (int mi = 0; mi < 2; mi++) {
                int mt = wm * 2 + mi;
                *(uint4*)a[mi] = *(const uint4*)&As[buf][((k8 * 8 + mt) * 32 + lane) * 4];
            }
            uint32_t b[NT][2];
            #pragma unroll
            for (int ni = 0; ni < NT; ni++) {
                int nt = wn * NT + ni;
                *(uint2*)b[ni] = *(const uint2*)&Bs[buf][((k8 * NTILES + nt) * 32 + lane) * 2];
            }
            #pragma unroll
            for (int mi = 0; mi < 2; mi++)
                #pragma unroll
                for (int ni = 0; ni < NT; ni++)
                    mma_tf32(acc[mi][ni], a[mi], b[ni]);
        }
        buf ^= 1;
    }

    // ---- epilogue ----
    #pragma unroll
    for (int mi = 0; mi < 2; mi++) {
        #pragma unroll
        for (int ni = 0; ni < NT; ni++) {
            int m_base = row0 + wm * 32 + mi * 16 + groupID;
            int n_base = col0 + wn * NT * 8 + ni * 8 + tig * 2;
            #pragma unroll
            for (int r = 0; r < 4; r++) {
                int gm = m_base + ((r >> 1) << 3);
                int gn = n_base + (r & 1);
                if (gn >= N) continue;
                float v = acc[mi][ni][r];
                if (MODE == 0) {
                    if (bias) v += biasScale * bias[gn];
                    C[(long long)gm * N + gn] = v;
                } else {
                    long long br = (long long)(gm >> 5) * biasStride + gn;
                    C [(long long)gm * N + gn] = tanhf(v + bias [br]);
                    C2[(long long)gm * N + gn] = tanhf(v + bias2[br]);
                }
            }
        }
    }
}

__global__ void reduce_add_kernel(const float* __restrict__ src, float* __restrict__ dst,
                                  int parts, long long len)
{
    long long i = (long long)blockIdx.x * 256 + threadIdx.x;
    if (i >= len) return;
    float s = 0.f;
    for (int p = 0; p < parts; p++) s += src[(long long)p * len + i];
    dst[i] = s;
}

// ---------------- stage kernels ----------------
__global__ void rep_kernel(const float* __restrict__ seq, const int* __restrict__ ep)
{
    int bn = blockIdx.x;
    int b = bn / NENT, n = bn % NENT;
    int e0 = ep[(b * NENT + n) * MENT + 0];
    int e1 = ep[(b * NENT + n) * MENT + 1];
    int e2 = ep[(b * NENT + n) * MENT + 2];
    int e3 = ep[(b * NENT + n) * MENT + 3];
    const float* sb = seq + (long long)b * SEQ * HID;
    for (int h = threadIdx.x; h < HID; h += blockDim.x) {
        float v0 = sb[(long long)e0 * HID + h];
        float v1 = sb[(long long)e1 * HID + h];
        float v2 = sb[(long long)e2 * HID + h];
        float v3 = sb[(long long)e3 * HID + h];
        float m = fmaxf(fmaxf(v0, v1), fmaxf(v2, v3));
        float s = expf(v0 - m) + expf(v1 - m) + expf(v2 - m) + expf(v3 - m);
        d_rep[(b * NENT + n) * HID + h] = m + logf(s);
    }
}

__global__ void packA_kernel(const float* __restrict__ A_bl)
{
    int idx = blockIdx.x * 256 + threadIdx.x;
    if (idx >= WD * PP) return;
    int o = idx / PP, pq = idx % PP;
    d_Ablt[pq * WD + o] = A_bl[idx];
}

__global__ void packW_kernel(const float* __restrict__ W_s, const float* __restrict__ W_o)
{
    int idx = blockIdx.x * 256 + threadIdx.x;
    if (idx >= WD * WD) return;
    int k = idx / WD, j = idx % WD;
    d_Wso[(long long)k * (2 * WD) + j]      = W_s[idx];
    d_Wso[(long long)k * (2 * WD) + WD + j] = W_o[idx];
}

__global__ void ga_kernel(const float* __restrict__ att, const int* __restrict__ ep)
{
    int b = blockIdx.z;
    int n = blockIdx.y / HEADS, h = blockIdx.y % HEADS;
    int s = blockIdx.x * blockDim.x + threadIdx.x;
    const float* ab = att + ((long long)(b * HEADS + h)) * SEQ * SEQ;
    float a = 0.f;
    #pragma unroll
    for (int m = 0; m < MENT; m++) {
        int e = ep[(b * NENT + n) * MENT + m];
        a += ab[(long long)e * SEQ + s];
    }
    d_ga[((long long)((b * NENT + n) * HEADS + h)) * SEQ + s] = a;
}

__global__ __launch_bounds__(256) void pa_kernel()
{
    int b = blockIdx.y;
    int ij = blockIdx.x;
    int i = ij >> 5, j = ij & 31;
    const float* gi = d_ga + ((long long)(b * NENT + i)) * HEADS * SEQ;
    const float* gj = d_ga + ((long long)(b * NENT + j)) * HEADS * SEQ;
    int tid = threadIdx.x;
    float acc[4];
    float lsum = 0.f;
    #pragma unroll
    for (int r = 0; r < 4; r++) {
        int s = r * 256 + tid;
        float a = 0.f;
        #pragma unroll
        for (int h = 0; h < HEADS; h++)
            a += gi[h * SEQ + s] * gj[h * SEQ + s];
        acc[r] = a;
        lsum += a;
    }
    __shared__ float red[256];
    red[tid] = lsum;
    __syncthreads();
    for (int off = 128; off > 0; off >>= 1) {
        if (tid < off) red[tid] += red[tid + off];
        __syncthreads();
    }
    float inv = 1.0f / red[0];
    float* po = d_pa + ((long long)(b * NPAIR + ij)) * SEQ;
    #pragma unroll
    for (int r = 0; r < 4; r++)
        po[r * 256 + tid] = acc[r] * inv;
}

__global__ __launch_bounds__(256) void P_kernel()
{
    __shared__ float zs[WD], zo[WD];
    long long row = blockIdx.x;
    for (int w = threadIdx.x; w < WD; w += 256) {
        zs[w] = d_Zs[row * WD + w];
        zo[w] = d_Zo[row * WD + w];
    }
    __syncthreads();
    int t = threadIdx.x;
    if (t < PP) {
        int p = t / DD, q = t % DD;
        float a = 0.f;
        #pragma unroll
        for (int k = 0; k < SPLITK; k++)
            a += zs[p * SPLITK + k] * zo[q * SPLITK + k];
        d_P[row * PP + t] = a;
    }
}

__global__ __launch_bounds__(256) void e_kernel(const float* __restrict__ v_attn)
{
    int row = blockIdx.x;
    int tid = threadIdx.x;
    float val = tanhf(d_t[(long long)row * AD + tid]) * v_attn[tid];
    __shared__ float red[256];
    red[tid] = val;
    __syncthreads();
    for (int off = 128; off > 0; off >>= 1) {
        if (tid < off) red[tid] += red[tid + off];
        __syncthreads();
    }
    if (tid == 0) d_e[row] = red[0];
}

__global__ __launch_bounds__(1024) void softmax_kernel()
{
    int b = blockIdx.x;
    int tid = threadIdx.x;
    int w = tid >> 5, lane = tid & 31;
    const float* eb = d_e + b * NPAIR;
    float v = eb[w * 32 + lane];
    float m = v;
    for (int o = 16; o > 0; o >>= 1) m = fmaxf(m, __shfl_xor_sync(~0u, m, o));
    float ex = expf(v - m);
    float s = ex;
    for (int o = 16; o > 0; o >>= 1) s += __shfl_xor_sync(~0u, s, o);
    d_arow[b * NPAIR + w * 32 + lane] = ex / s;
    float v2 = eb[lane * 32 + w];
    float m2 = v2;
    for (int o = 16; o > 0; o >>= 1) m2 = fmaxf(m2, __shfl_xor_sync(~0u, m2, o));
    float ex2 = expf(v2 - m2);
    float s2 = ex2;
    for (int o = 16; o > 0; o >>= 1) s2 += __shfl_xor_sync(~0u, s2, o);
    d_acol[b * NPAIR + lane * 32 + w] = ex2 / s2;
}

__global__ void rowcolC_kernel()
{
    int b = blockIdx.y, n = blockIdx.x;
    int c = threadIdx.x;
    if (c >= NC) return;
    const float* gc = d_gclf + (long long)b * NPAIR * NC;
    float rs = 0.f, cs = 0.f;
    #pragma unroll 4
    for (int k = 0; k < NENT; k++) {
        rs += d_arow[b * NPAIR + n * 32 + k] * gc[(long long)(n * 32 + k) * NC + c];
        cs += d_acol[b * NPAIR + k * 32 + n] * gc[(long long)(k * 32 + n) * NC + c];
    }
    d_rgcg[(b * NENT + n) * NC + c] = rs;
    d_rgcg[(BATCH * NENT + b * NENT + n) * NC + c] = cs;
}

__global__ void final_kernel(const float* __restrict__ clf_b, float* __restrict__ out)
{
    long long idx = (long long)blockIdx.x * blockDim.x + threadIdx.x;
    const long long total = (long long)BATCH * NPAIR * NC;
    if (idx >= total) return;
    int c = (int)(idx % NC);
    long long rb = idx / NC;
    int ij = (int)(rb % NPAIR);
    int b = (int)(rb / NPAIR);
    int i = ij >> 5, j = ij & 31;
    out[idx] = d_gclf[idx]
             + d_rgcg[(b * NENT + i) * NC + c]
             + d_rgcg[(BATCH * NENT + b * NENT + j) * NC + c]
             + clf_b[c];
}

// ---------------- host launch ----------------
extern "C" void kernel_launch(void* const* d_in, const int* in_sizes, int n_in,
                              void* d_out, int out_size)
{
    const float* seq    = (const float*)d_in[0];
    const float* att    = (const float*)d_in[1];
    const int*   ep     = (const int*)  d_in[2];
    const float* W_s    = (const float*)d_in[3];
    const float* W_o    = (const float*)d_in[4];
    const float* W_c    = (const float*)d_in[5];
    const float* A_bl   = (const float*)d_in[6];
    const float* b_bl   = (const float*)d_in[7];
    const float* W_attn = (const float*)d_in[8];
    const float* v_attn = (const float*)d_in[9];
    const float* clf_W  = (const float*)d_in[10];
    const float* clf_b  = (const float*)d_in[11];
    float* out = (float*)d_out;

    float *p_rep, *p_rso, *p_Wso, *p_pa, *p_ctxh, *p_Zs, *p_Zo, *p_P, *p_Ablt,
          *p_g, *p_t, *p_gclf, *p_part;
    cudaGetSymbolAddress((void**)&p_rep,  d_rep);
    cudaGetSymbolAddress((void**)&p_rso,  d_rso);
    cudaGetSymbolAddress((void**)&p_Wso,  d_Wso);
    cudaGetSymbolAddress((void**)&p_pa,   d_pa);
    cudaGetSymbolAddress((void**)&p_ctxh, d_ctxh);
    cudaGetSymbolAddress((void**)&p_Zs,   d_Zs);
    cudaGetSymbolAddress((void**)&p_Zo,   d_Zo);
    cudaGetSymbolAddress((void**)&p_P,    d_P);
    cudaGetSymbolAddress((void**)&p_Ablt, d_Ablt);
    cudaGetSymbolAddress((void**)&p_g,    d_g);
    cudaGetSymbolAddress((void**)&p_t,    d_t);
    cudaGetSymbolAddress((void**)&p_gclf, d_gclf);
    cudaGetSymbolAddress((void**)&p_part, d_part);

    // 1. entity reps
    rep_kernel<<<BATCH * NENT, 256>>>(seq, ep);
    // 2-3. packs
    packA_kernel<<<(WD * PP + 255) / 256, 256>>>(A_bl);
    packW_kernel<<<(WD * WD + 255) / 256, 256>>>(W_s, W_o);
    // 4. entity attention gather
    {
        dim3 grid(SEQ / 256, NENT * HEADS, BATCH);
        ga_kernel<<<grid, 256>>>(att, ep);
    }
    // 5. pairwise localized attention
    {
        dim3 grid(NPAIR, BATCH);
        pa_kernel<<<grid, 256>>>();
    }
    // 6. ctxh = pa @ seq  (batched)  [1024,768,1024] x4   NT=8 -> grid 192
    {
        dim3 grid(WD / 128, NPAIR / 128, BATCH);
        mma_gemm<8, 0><<<grid, 256>>>(p_pa, seq, p_ctxh, nullptr,
                                      NPAIR, HID, SEQ,
                                      (long long)NPAIR * SEQ, (long long)SEQ * HID,
                                      (long long)NPAIR * HID,
                                      1, 0, nullptr, 0.f, nullptr, 0);
    }
    // 7. rso partials = rep @ [W_s|W_o]  (split-K 6)  [128,1536,768]
    {
        dim3 grid((2 * WD) / 128, 1, 6);
        mma_gemm<8, 0><<<grid, 256>>>(p_rep, p_Wso, p_part, nullptr,
                                      BATCH * NENT, 2 * WD, HID, 0, 0, 0,
                                      6, (long long)BATCH * NENT * 2 * WD,
                                      nullptr, 0.f, nullptr, 0);
    }
    // 8. reduce rso
    reduce_add_kernel<<<(BATCH * NENT * 2 * WD + 255) / 256, 256>>>(
        p_part, p_rso, 6, (long long)BATCH * NENT * 2 * WD);
    // 9. fused: Zs/Zo = tanh(rso[i] + ctxh @ W_c)  [4096,768,768]  NT=8 -> 192
    {
        dim3 grid(WD / 128, (BATCH * NPAIR) / 128, 1);
        mma_gemm<8, 1><<<grid, 256>>>(p_ctxh, W_c, p_Zs, p_Zo,
                                      BATCH * NPAIR, WD, HID, 0, 0, 0,
                                      1, 0, p_rso, 0.f, p_rso + WD, 2 * WD);
    }
    // 10. P
    P_kernel<<<BATCH * NPAIR, 256>>>();
    // 11. g = P @ A_bl^T + 64*b_bl  [4096,768,144]  NT=8 -> 192
    {
        dim3 grid(WD / 128, (BATCH * NPAIR) / 128, 1);
        mma_gemm<8, 0><<<grid, 256>>>(p_P, p_Ablt, p_g, nullptr,
                                      BATCH * NPAIR, WD, PP, 0, 0, 0,
                                      1, 0, b_bl, (float)SPLITK, nullptr, 0);
    }
    // 12. t = g @ W_attn  [4096,256,768]  NT=4 -> grid 128
    {
        dim3 grid(AD / 64, (BATCH * NPAIR) / 128, 1);
        mma_gemm<4, 0><<<grid, 256>>>(p_g, W_attn, p_t, nullptr,
                                      BATCH * NPAIR, AD, WD, 0, 0, 0,
                                      1, 0, nullptr, 0.f, nullptr, 0);
    }
    // 13. e = tanh(t) . v_attn
    e_kernel<<<BATCH * NPAIR, 256>>>(v_attn);
    // 14. softmax
    softmax_kernel<<<BATCH, 1024>>>();
    // 15. gclf partials = g @ clf_W (split-K 4)  [4096,97,768]  NT=4 -> 256
    {
        long long len = (long long)BATCH * NPAIR * NC;
        dim3 grid((NC + 63) / 64, (BATCH * NPAIR) / 128, 4);
        mma_gemm<4, 0><<<grid, 256>>>(p_g, clf_W, p_part, nullptr,
                                      BATCH * NPAIR, NC, WD, 0, 0, 0,
                                      4, len, nullptr, 0.f, nullptr, 0);
        reduce_add_kernel<<<(unsigned)((len + 255) / 256), 256>>>(p_part, p_gclf, 4, len);
    }
    // 16. axis-attention residual folded through clf_W
    {
        dim3 grid(NENT, BATCH);
        rowcolC_kernel<<<grid, 128>>>();
    }
    // 17. out
    {
        long long total = (long long)BATCH * NPAIR * NC;
        final_kernel<<<(unsigned)((total + 255) / 256), 256>>>(clf_b, out);
    }
}

// round 5
// speedup vs baseline: 1.3073x; 1.3073x over previous
#include <cuda_runtime.h>
#include <math.h>
#include <stdint.h>

#define BATCH 4
#define SEQ   1024
#define HID   768
#define HEADS 12
#define NENT  32
#define MENT  4
#define WD    768
#define AD    256
#define NC    97
#define SPLITK 64
#define DD    12
#define PP    144          // DD*DD
#define NPAIR (NENT*NENT)  // 1024

// ---------------- device scratch ----------------
__device__ float d_rep[BATCH*NENT*HID];
__device__ float d_rso[BATCH*NENT*2*WD];          // [128][1536] : rs | ro
__device__ float d_Wso[WD*2*WD];                  // [768][1536] : W_s | W_o
__device__ float d_ga [BATCH*NENT*HEADS*SEQ];
__device__ float d_pa [(size_t)BATCH*NPAIR*SEQ];
__device__ float d_ctxh[(size_t)BATCH*NPAIR*HID];
__device__ float d_Zs [(size_t)BATCH*NPAIR*WD];
__device__ float d_Zo [(size_t)BATCH*NPAIR*WD];
__device__ float d_P  [(size_t)BATCH*NPAIR*PP];
__device__ float d_g  [(size_t)BATCH*NPAIR*WD];
__device__ float d_t  [(size_t)BATCH*NPAIR*AD];
__device__ float d_e  [BATCH*NPAIR];
__device__ float d_arow[BATCH*NPAIR];
__device__ float d_acol[BATCH*NPAIR];
__device__ float d_Ablt[PP*WD];
__device__ float d_gclf[(size_t)BATCH*NPAIR*NC];
__device__ float d_rgcg[2*BATCH*NENT*NC];
__device__ float d_part[1700000];                 // split-K partials

// ---------------- tf32 helpers ----------------
__device__ __forceinline__ uint32_t f2tf32(float x)
{
    uint32_t r;
    asm("cvt.rna.tf32.f32 %0, %1;" : "=r"(r) : "f"(x));
    return r;
}

__device__ __forceinline__ void mma_tf32(float* c, const uint32_t* a, const uint32_t* b)
{
    asm volatile(
        "mma.sync.aligned.m16n8k8.row.col.f32.tf32.tf32.f32 "
        "{%0,%1,%2,%3}, {%4,%5,%6,%7}, {%8,%9}, {%0,%1,%2,%3};"
        : "+f"(c[0]), "+f"(c[1]), "+f"(c[2]), "+f"(c[3])
        : "r"(a[0]), "r"(a[1]), "r"(a[2]), "r"(a[3]), "r"(b[0]), "r"(b[1]));
}

// ---------------- pipelined tf32 tensor-core GEMM (BM=128, BN=64, BK=16) ----------------
// C[M,N] = A[M,K] row * B[K,N] row. 256 thr = 8 warps (4 m-warps x 2 n-warps),
// warp tile 32x32 = 2 m16 x 4 n8 tiles. Fragment-order smem, tf32 convert at
// smem store. Ping-pong smem + register staging: one sync per iteration,
// gmem latency overlapped with MMA compute. ~95 regs -> 2 blocks/SM.
// MODE 0: C = acc (+ biasScale*bias[n] if bias).
// MODE 1: C = tanh(acc + bias[(gm>>5)*biasStride+gn]); C2 likewise with bias2.
// Requirements: M%128==0, (K/kSplit)%16==0.
template<int MODE>
__global__ __launch_bounds__(256)
void mma_gemm(const float* __restrict__ A, const float* __restrict__ B,
              float* __restrict__ C, float* __restrict__ C2,
              int M, int N, int K,
              long long sA, long long sB, long long sC,
              int kSplit, long long partStride,
              const float* __restrict__ bias, float biasScale,
              const float* __restrict__ bias2, int biasStride)
{
    __shared__ uint32_t As[2][2 * 8 * 32 * 4];   // 2 x 8KB
    __shared__ uint32_t Bs[2][2 * 8 * 32 * 2];   // 2 x 4KB

    int zb = blockIdx.z / kSplit;
    int kz = blockIdx.z - zb * kSplit;
    A += (long long)zb * sA;
    B += (long long)zb * sB;
    C += (long long)zb * sC + (long long)kz * partStride;

    int row0 = blockIdx.y * 128;
    int col0 = blockIdx.x * 64;
    int tid = threadIdx.x, lane = tid & 31, w = tid >> 5;
    int wm = w & 3, wn = w >> 2;
    int groupID = lane >> 2, tig = lane & 3;

    int kLen = K / kSplit;
    int k0beg = kz * kLen, k0end = k0beg + kLen;

    float acc[2][4][4];
    #pragma unroll
    for (int i = 0; i < 2; i++)
        #pragma unroll
        for (int j = 0; j < 4; j++)
            #pragma unroll
            for (int r = 0; r < 4; r++) acc[i][j][r] = 0.f;

    const bool nvec = ((N & 3) == 0);

    float4 va[2], vb;

    // precomputed load indices
    int am0 = tid >> 2, akq = tid & 3;            // A: thread covers (m, kq) and (m+64, kq)
    int bkl = tid >> 4, bnq = tid & 15;           // B: thread covers (k_local, nq)

    // ---- prefetch first tiles ----
    {
        int kk = k0beg;
        va[0] = *(const float4*)(A + (long long)(row0 + am0) * K + kk + akq * 4);
        va[1] = *(const float4*)(A + (long long)(row0 + am0 + 64) * K + kk + akq * 4);
        if (nvec) {
            vb = *(const float4*)(B + (long long)(kk + bkl) * N + col0 + bnq * 4);
        } else {
            const float* bp = B + (long long)(kk + bkl) * N;
            int n0 = col0 + bnq * 4;
            vb.x = (n0 + 0 < N) ? bp[n0 + 0] : 0.f;
            vb.y = (n0 + 1 < N) ? bp[n0 + 1] : 0.f;
            vb.z = (n0 + 2 < N) ? bp[n0 + 2] : 0.f;
            vb.w = (n0 + 3 < N) ? bp[n0 + 3] : 0.f;
        }
    }

    int buf = 0;
    for (int k0 = k0beg; k0 < k0end; k0 += 16) {
        // ---- store staged tiles to smem (tf32, fragment order) ----
        #pragma unroll
        for (int i = 0; i < 2; i++) {
            int m = am0 + i * 64;
            int mt = m >> 4, row = m & 15;
            int k8 = akq >> 1;
            int reg = (row >> 3) + ((akq & 1) << 1);
            int base = (((k8 * 8 + mt) * 32) + (row & 7) * 4) * 4 + reg;
            As[buf][base + 0]  = f2tf32(va[i].x);
            As[buf][base + 4]  = f2tf32(va[i].y);
            As[buf][base + 8]  = f2tf32(va[i].z);
            As[buf][base + 12] = f2tf32(va[i].w);
        }
        {
            int k8 = bkl >> 3;
            int reg = (bkl >> 2) & 1;
            int ktig = bkl & 3;
            int nt = (bnq * 4) >> 3;
            int gbase = (bnq * 4) & 7;
            int base = (((k8 * 8 + nt) * 32) + gbase * 4 + ktig) * 2 + reg;
            Bs[buf][base + 0]  = f2tf32(vb.x);
            Bs[buf][base + 8]  = f2tf32(vb.y);
            Bs[buf][base + 16] = f2tf32(vb.z);
            Bs[buf][base + 24] = f2tf32(vb.w);
        }
        __syncthreads();

        // ---- prefetch next iteration while computing this one ----
        int kn = k0 + 16;
        if (kn < k0end) {
            va[0] = *(const float4*)(A + (long long)(row0 + am0) * K + kn + akq * 4);
            va[1] = *(const float4*)(A + (long long)(row0 + am0 + 64) * K + kn + akq * 4);
            if (nvec) {
                vb = *(const float4*)(B + (long long)(kn + bkl) * N + col0 + bnq * 4);
            } else {
                const float* bp = B + (long long)(kn + bkl) * N;
                int n0 = col0 + bnq * 4;
                vb.x = (n0 + 0 < N) ? bp[n0 + 0] : 0.f;
                vb.y = (n0 + 1 < N) ? bp[n0 + 1] : 0.f;
                vb.z = (n0 + 2 < N) ? bp[n0 + 2] : 0.f;
                vb.w = (n0 + 3 < N) ? bp[n0 + 3] : 0.f;
            }
        }

        // ---- compute ----
        #pragma unroll
        for (int k8 = 0; k8 < 2; k8++) {
            uint32_t a[2][4];
            #pragma unroll
            for (int mi = 0; mi < 2; mi++) {
                int mt = wm * 2 + mi;
                *(uint4*)a[mi] = *(const uint4*)&As[buf][((k8 * 8 + mt) * 32 + lane) * 4];
            }
            uint32_t b[4][2];
            #pragma unroll
            for (int ni = 0; ni < 4; ni++) {
                int nt = wn * 4 + ni;
                *(uint2*)b[ni] = *(const uint2*)&Bs[buf][((k8 * 8 + nt) * 32 + lane) * 2];
            }
            #pragma unroll
            for (int mi = 0; mi < 2; mi++)
                #pragma unroll
                for (int ni = 0; ni < 4; ni++)
                    mma_tf32(acc[mi][ni], a[mi], b[ni]);
        }
        buf ^= 1;
    }

    // ---- epilogue ----
    #pragma unroll
    for (int mi = 0; mi < 2; mi++) {
        #pragma unroll
        for (int ni = 0; ni < 4; ni++) {
            int m_base = row0 + wm * 32 + mi * 16 + groupID;
            int n_base = col0 + wn * 32 + ni * 8 + tig * 2;
            #pragma unroll
            for (int r = 0; r < 4; r++) {
                int gm = m_base + ((r >> 1) << 3);
                int gn = n_base + (r & 1);
                if (gn >= N) continue;
                float v = acc[mi][ni][r];
                if (MODE == 0) {
                    if (bias) v += biasScale * bias[gn];
                    C[(long long)gm * N + gn] = v;
                } else {
                    long long br = (long long)(gm >> 5) * biasStride + gn;
                    C [(long long)gm * N + gn] = tanhf(v + bias [br]);
                    C2[(long long)gm * N + gn] = tanhf(v + bias2[br]);
                }
            }
        }
    }
}

__global__ void reduce_add_kernel(const float* __restrict__ src, float* __restrict__ dst,
                                  int parts, long long len)
{
    long long i = (long long)blockIdx.x * 256 + threadIdx.x;
    if (i >= len) return;
    float s = 0.f;
    for (int p = 0; p < parts; p++) s += src[(long long)p * len + i];
    dst[i] = s;
}

// ---------------- stage kernels ----------------
__global__ void rep_kernel(const float* __restrict__ seq, const int* __restrict__ ep)
{
    int bn = blockIdx.x;
    int b = bn / NENT, n = bn % NENT;
    int e0 = ep[(b * NENT + n) * MENT + 0];
    int e1 = ep[(b * NENT + n) * MENT + 1];
    int e2 = ep[(b * NENT + n) * MENT + 2];
    int e3 = ep[(b * NENT + n) * MENT + 3];
    const float* sb = seq + (long long)b * SEQ * HID;
    for (int h = threadIdx.x; h < HID; h += blockDim.x) {
        float v0 = sb[(long long)e0 * HID + h];
        float v1 = sb[(long long)e1 * HID + h];
        float v2 = sb[(long long)e2 * HID + h];
        float v3 = sb[(long long)e3 * HID + h];
        float m = fmaxf(fmaxf(v0, v1), fmaxf(v2, v3));
        float s = expf(v0 - m) + expf(v1 - m) + expf(v2 - m) + expf(v3 - m);
        d_rep[(b * NENT + n) * HID + h] = m + logf(s);
    }
}

__global__ void packA_kernel(const float* __restrict__ A_bl)
{
    int idx = blockIdx.x * 256 + threadIdx.x;
    if (idx >= WD * PP) return;
    int o = idx / PP, pq = idx % PP;
    d_Ablt[pq * WD + o] = A_bl[idx];
}

__global__ void packW_kernel(const float* __restrict__ W_s, const float* __restrict__ W_o)
{
    int idx = blockIdx.x * 256 + threadIdx.x;
    if (idx >= WD * WD) return;
    int k = idx / WD, j = idx % WD;
    d_Wso[(long long)k * (2 * WD) + j]      = W_s[idx];
    d_Wso[(long long)k * (2 * WD) + WD + j] = W_o[idx];
}

__global__ void ga_kernel(const float* __restrict__ att, const int* __restrict__ ep)
{
    int b = blockIdx.z;
    int n = blockIdx.y / HEADS, h = blockIdx.y % HEADS;
    int s = blockIdx.x * blockDim.x + threadIdx.x;
    const float* ab = att + ((long long)(b * HEADS + h)) * SEQ * SEQ;
    float a = 0.f;
    #pragma unroll
    for (int m = 0; m < MENT; m++) {
        int e = ep[(b * NENT + n) * MENT + m];
        a += ab[(long long)e * SEQ + s];
    }
    d_ga[((long long)((b * NENT + n) * HEADS + h)) * SEQ + s] = a;
}

__global__ __launch_bounds__(256) void pa_kernel()
{
    int b = blockIdx.y;
    int ij = blockIdx.x;
    int i = ij >> 5, j = ij & 31;
    const float* gi = d_ga + ((long long)(b * NENT + i)) * HEADS * SEQ;
    const float* gj = d_ga + ((long long)(b * NENT + j)) * HEADS * SEQ;
    int tid = threadIdx.x;
    float acc[4];
    float lsum = 0.f;
    #pragma unroll
    for (int r = 0; r < 4; r++) {
        int s = r * 256 + tid;
        float a = 0.f;
        #pragma unroll
        for (int h = 0; h < HEADS; h++)
            a += gi[h * SEQ + s] * gj[h * SEQ + s];
        acc[r] = a;
        lsum += a;
    }
    __shared__ float red[256];
    red[tid] = lsum;
    __syncthreads();
    for (int off = 128; off > 0; off >>= 1) {
        if (tid < off) red[tid] += red[tid + off];
        __syncthreads();
    }
    float inv = 1.0f / red[0];
    float* po = d_pa + ((long long)(b * NPAIR + ij)) * SEQ;
    #pragma unroll
    for (int r = 0; r < 4; r++)
        po[r * 256 + tid] = acc[r] * inv;
}

__global__ __launch_bounds__(256) void P_kernel()
{
    __shared__ float zs[WD], zo[WD];
    long long row = blockIdx.x;
    for (int w = threadIdx.x; w < WD; w += 256) {
        zs[w] = d_Zs[row * WD + w];
        zo[w] = d_Zo[row * WD + w];
    }
    __syncthreads();
    int t = threadIdx.x;
    if (t < PP) {
        int p = t / DD, q = t % DD;
        float a = 0.f;
        #pragma unroll
        for (int k = 0; k < SPLITK; k++)
            a += zs[p * SPLITK + k] * zo[q * SPLITK + k];
        d_P[row * PP + t] = a;
    }
}

__global__ __launch_bounds__(256) void e_kernel(const float* __restrict__ v_attn)
{
    int row = blockIdx.x;
    int tid = threadIdx.x;
    float val = tanhf(d_t[(long long)row * AD + tid]) * v_attn[tid];
    __shared__ float red[256];
    red[tid] = val;
    __syncthreads();
    for (int off = 128; off > 0; off >>= 1) {
        if (tid < off) red[tid] += red[tid + off];
        __syncthreads();
    }
    if (tid == 0) d_e[row] = red[0];
}

__global__ __launch_bounds__(1024) void softmax_kernel()
{
    int b = blockIdx.x;
    int tid = threadIdx.x;
    int w = tid >> 5, lane = tid & 31;
    const float* eb = d_e + b * NPAIR;
    float v = eb[w * 32 + lane];
    float m = v;
    for (int o = 16; o > 0; o >>= 1) m = fmaxf(m, __shfl_xor_sync(~0u, m, o));
    float ex = expf(v - m);
    float s = ex;
    for (int o = 16; o > 0; o >>= 1) s += __shfl_xor_sync(~0u, s, o);
    d_arow[b * NPAIR + w * 32 + lane] = ex / s;
    float v2 = eb[lane * 32 + w];
    float m2 = v2;
    for (int o = 16; o > 0; o >>= 1) m2 = fmaxf(m2, __shfl_xor_sync(~0u, m2, o));
    float ex2 = expf(v2 - m2);
    float s2 = ex2;
    for (int o = 16; o > 0; o >>= 1) s2 += __shfl_xor_sync(~0u, s2, o);
    d_acol[b * NPAIR + lane * 32 + w] = ex2 / s2;
}

__global__ void rowcolC_kernel()
{
    int b = blockIdx.y, n = blockIdx.x;
    int c = threadIdx.x;
    if (c >= NC) return;
    const float* gc = d_gclf + (long long)b * NPAIR * NC;
    float rs = 0.f, cs = 0.f;
    #pragma unroll 4
    for (int k = 0; k < NENT; k++) {
        rs += d_arow[b * NPAIR + n * 32 + k] * gc[(long long)(n * 32 + k) * NC + c];
        cs += d_acol[b * NPAIR + k * 32 + n] * gc[(long long)(k * 32 + n) * NC + c];
    }
    d_rgcg[(b * NENT + n) * NC + c] = rs;
    d_rgcg[(BATCH * NENT + b * NENT + n) * NC + c] = cs;
}

__global__ void final_kernel(const float* __restrict__ clf_b, float* __restrict__ out)
{
    long long idx = (long long)blockIdx.x * blockDim.x + threadIdx.x;
    const long long total = (long long)BATCH * NPAIR * NC;
    if (idx >= total) return;
    int c = (int)(idx % NC);
    long long rb = idx / NC;
    int ij = (int)(rb % NPAIR);
    int b = (int)(rb / NPAIR);
    int i = ij >> 5, j = ij & 31;
    out[idx] = d_gclf[idx]
             + d_rgcg[(b * NENT + i) * NC + c]
             + d_rgcg[(BATCH * NENT + b * NENT + j) * NC + c]
             + clf_b[c];
}

// ---------------- host launch ----------------
extern "C" void kernel_launch(void* const* d_in, const int* in_sizes, int n_in,
                              void* d_out, int out_size)
{
    const float* seq    = (const float*)d_in[0];
    const float* att    = (const float*)d_in[1];
    const int*   ep     = (const int*)  d_in[2];
    const float* W_s    = (const float*)d_in[3];
    const float* W_o    = (const float*)d_in[4];
    const float* W_c    = (const float*)d_in[5];
    const float* A_bl   = (const float*)d_in[6];
    const float* b_bl   = (const float*)d_in[7];
    const float* W_attn = (const float*)d_in[8];
    const float* v_attn = (const float*)d_in[9];
    const float* clf_W  = (const float*)d_in[10];
    const float* clf_b  = (const float*)d_in[11];
    float* out = (float*)d_out;

    float *p_rep, *p_rso, *p_Wso, *p_pa, *p_ctxh, *p_Zs, *p_Zo, *p_P, *p_Ablt,
          *p_g, *p_t, *p_gclf, *p_part;
    cudaGetSymbolAddress((void**)&p_rep,  d_rep);
    cudaGetSymbolAddress((void**)&p_rso,  d_rso);
    cudaGetSymbolAddress((void**)&p_Wso,  d_Wso);
    cudaGetSymbolAddress((void**)&p_pa,   d_pa);
    cudaGetSymbolAddress((void**)&p_ctxh, d_ctxh);
    cudaGetSymbolAddress((void**)&p_Zs,   d_Zs);
    cudaGetSymbolAddress((void**)&p_Zo,   d_Zo);
    cudaGetSymbolAddress((void**)&p_P,    d_P);
    cudaGetSymbolAddress((void**)&p_Ablt, d_Ablt);
    cudaGetSymbolAddress((void**)&p_g,    d_g);
    cudaGetSymbolAddress((void**)&p_t,    d_t);
    cudaGetSymbolAddress((void**)&p_gclf, d_gclf);
    cudaGetSymbolAddress((void**)&p_part, d_part);

    // 1. entity reps
    rep_kernel<<<BATCH * NENT, 256>>>(seq, ep);
    // 2-3. packs
    packA_kernel<<<(WD * PP + 255) / 256, 256>>>(A_bl);
    packW_kernel<<<(WD * WD + 255) / 256, 256>>>(W_s, W_o);
    // 4. entity attention gather
    {
        dim3 grid(SEQ / 256, NENT * HEADS, BATCH);
        ga_kernel<<<grid, 256>>>(att, ep);
    }
    // 5. pairwise localized attention
    {
        dim3 grid(NPAIR, BATCH);
        pa_kernel<<<grid, 256>>>();
    }
    // 6. ctxh = pa @ seq  (batched)  [1024,768,1024] x4  -> grid 384
    {
        dim3 grid(WD / 64, NPAIR / 128, BATCH);
        mma_gemm<0><<<grid, 256>>>(p_pa, seq, p_ctxh, nullptr,
                                   NPAIR, HID, SEQ,
                                   (long long)NPAIR * SEQ, (long long)SEQ * HID,
                                   (long long)NPAIR * HID,
                                   1, 0, nullptr, 0.f, nullptr, 0);
    }
    // 7. rso partials = rep @ [W_s|W_o]  (split-K 6)  [128,1536,768] -> 144
    {
        dim3 grid((2 * WD) / 64, 1, 6);
        mma_gemm<0><<<grid, 256>>>(p_rep, p_Wso, p_part, nullptr,
                                   BATCH * NENT, 2 * WD, HID, 0, 0, 0,
                                   6, (long long)BATCH * NENT * 2 * WD,
                                   nullptr, 0.f, nullptr, 0);
    }
    // 8. reduce rso
    reduce_add_kernel<<<(BATCH * NENT * 2 * WD + 255) / 256, 256>>>(
        p_part, p_rso, 6, (long long)BATCH * NENT * 2 * WD);
    // 9. fused: Zs/Zo = tanh(rso[i] + ctxh @ W_c)  [4096,768,768] -> 384
    {
        dim3 grid(WD / 64, (BATCH * NPAIR) / 128, 1);
        mma_gemm<1><<<grid, 256>>>(p_ctxh, W_c, p_Zs, p_Zo,
                                   BATCH * NPAIR, WD, HID, 0, 0, 0,
                                   1, 0, p_rso, 0.f, p_rso + WD, 2 * WD);
    }
    // 10. P
    P_kernel<<<BATCH * NPAIR, 256>>>();
    // 11. g = P @ A_bl^T + 64*b_bl  [4096,768,144] -> 384
    {
        dim3 grid(WD / 64, (BATCH * NPAIR) / 128, 1);
        mma_gemm<0><<<grid, 256>>>(p_P, p_Ablt, p_g, nullptr,
                                   BATCH * NPAIR, WD, PP, 0, 0, 0,
                                   1, 0, b_bl, (float)SPLITK, nullptr, 0);
    }
    // 12. t = g @ W_attn  [4096,256,768] -> 128
    {
        dim3 grid(AD / 64, (BATCH * NPAIR) / 128, 1);
        mma_gemm<0><<<grid, 256>>>(p_g, W_attn, p_t, nullptr,
                                   BATCH * NPAIR, AD, WD, 0, 0, 0,
                                   1, 0, nullptr, 0.f, nullptr, 0);
    }
    // 13. e = tanh(t) . v_attn
    e_kernel<<<BATCH * NPAIR, 256>>>(v_attn);
    // 14. softmax
    softmax_kernel<<<BATCH, 1024>>>();
    // 15. gclf partials = g @ clf_W (split-K 4)  [4096,97,768] -> 256
    {
        long long len = (long long)BATCH * NPAIR * NC;
        dim3 grid((NC + 63) / 64, (BATCH * NPAIR) / 128, 4);
        mma_gemm<0><<<grid, 256>>>(p_g, clf_W, p_part, nullptr,
                                   BATCH * NPAIR, NC, WD, 0, 0, 0,
                                   4, len, nullptr, 0.f, nullptr, 0);
        reduce_add_kernel<<<(unsigned)((len + 255) / 256), 256>>>(p_part, p_gclf, 4, len);
    }
    // 16. axis-attention residual folded through clf_W
    {
        dim3 grid(NENT, BATCH);
        rowcolC_kernel<<<grid, 128>>>();
    }
    // 17. out
    {
        long long total = (long long)BATCH * NPAIR * NC;
        final_kernel<<<(unsigned)((total + 255) / 256), 256>>>(clf_b, out);
    }
}

// round 6
// speedup vs baseline: 2.0210x; 1.5459x over previous
#include <cuda_runtime.h>
#include <math.h>
#include <stdint.h>

#define BATCH 4
#define SEQ   1024
#define HID   768
#define HEADS 12
#define NENT  32
#define MENT  4
#define WD    768
#define AD    256
#define NC    97
#define SPLITK 64
#define DD    12
#define PP    144          // DD*DD
#define NPAIR (NENT*NENT)  // 1024

// ---------------- device scratch ----------------
__device__ float d_rep[BATCH*NENT*HID];
__device__ float d_rso[BATCH*NENT*2*WD];          // [128][1536] : rs | ro
__device__ float d_Wso[WD*2*WD];                  // [768][1536] : W_s | W_o
__device__ float d_ga [BATCH*NENT*HEADS*SEQ];
__device__ float d_pa [(size_t)BATCH*NPAIR*SEQ];
__device__ float d_ctxh[(size_t)BATCH*NPAIR*HID];
__device__ float d_Zs [(size_t)BATCH*NPAIR*WD];
__device__ float d_Zo [(size_t)BATCH*NPAIR*WD];
__device__ float d_P  [(size_t)BATCH*NPAIR*PP];
__device__ float d_g  [(size_t)BATCH*NPAIR*WD];
__device__ float d_t  [(size_t)BATCH*NPAIR*AD];
__device__ float d_e  [BATCH*NPAIR];
__device__ float d_arow[BATCH*NPAIR];
__device__ float d_acol[BATCH*NPAIR];
__device__ float d_Ablt[PP*WD];
__device__ float d_gclf[(size_t)BATCH*NPAIR*NC];
__device__ float d_rgcg[2*BATCH*NENT*NC];
__device__ float d_part[1700000];                 // split-K partials

// ---------------- tf32 helpers ----------------
__device__ __forceinline__ uint32_t f2tf32(float x)
{
    uint32_t r;
    asm("cvt.rna.tf32.f32 %0, %1;" : "=r"(r) : "f"(x));
    return r;
}

__device__ __forceinline__ void mma_tf32(float* c, const uint32_t* a, const uint32_t* b)
{
    asm volatile(
        "mma.sync.aligned.m16n8k8.row.col.f32.tf32.tf32.f32 "
        "{%0,%1,%2,%3}, {%4,%5,%6,%7}, {%8,%9}, {%0,%1,%2,%3};"
        : "+f"(c[0]), "+f"(c[1]), "+f"(c[2]), "+f"(c[3])
        : "r"(a[0]), "r"(a[1]), "r"(a[2]), "r"(a[3]), "r"(b[0]), "r"(b[1]));
}

// ---------------- pipelined tf32 tensor-core GEMM (BM=128, BN=64, BK=16) ----------------
// C[M,N] = A[M,K] row * B[K,N] row. 256 thr = 8 warps (4 m-warps x 2 n-warps),
// warp tile 32x32 = 2 m16 x 4 n8 tiles. Canonical padded smem layouts:
//   As[128][20]: STS.128 stores (<=2-way), fragment LDS.32 conflict-free.
//   Bs[16][72] : STS.128 stores conflict-free, fragment LDS.32 conflict-free.
// Ping-pong smem + register staging; one sync/iter; tf32 convert at smem store.
// MODE 0: C = acc (+ biasScale*bias[n] if bias).
// MODE 1: C = tanh(acc + bias[(gm>>5)*biasStride+gn]); C2 likewise with bias2.
// Requirements: M%128==0, (K/kSplit)%16==0.
#define AS_STRIDE 20
#define BS_STRIDE 72
template<int MODE>
__global__ __launch_bounds__(256)
void mma_gemm(const float* __restrict__ A, const float* __restrict__ B,
              float* __restrict__ C, float* __restrict__ C2,
              int M, int N, int K,
              long long sA, long long sB, long long sC,
              int kSplit, long long partStride,
              const float* __restrict__ bias, float biasScale,
              const float* __restrict__ bias2, int biasStride)
{
    __shared__ uint32_t As[2][128 * AS_STRIDE];   // 2 x 10.0 KB
    __shared__ uint32_t Bs[2][16 * BS_STRIDE];    // 2 x 4.5 KB

    int zb = blockIdx.z / kSplit;
    int kz = blockIdx.z - zb * kSplit;
    A += (long long)zb * sA;
    B += (long long)zb * sB;
    C += (long long)zb * sC + (long long)kz * partStride;

    int row0 = blockIdx.y * 128;
    int col0 = blockIdx.x * 64;
    int tid = threadIdx.x, lane = tid & 31, w = tid >> 5;
    int wm = w & 3, wn = w >> 2;
    int g = lane >> 2, t = lane & 3;

    int kLen = K / kSplit;
    int k0beg = kz * kLen, k0end = k0beg + kLen;

    float acc[2][4][4];
    #pragma unroll
    for (int i = 0; i < 2; i++)
        #pragma unroll
        for (int j = 0; j < 4; j++)
            #pragma unroll
            for (int r = 0; r < 4; r++) acc[i][j][r] = 0.f;

    const bool nvec = ((N & 3) == 0);

    float4 va[2], vb;

    // load indices: A thread covers rows am0 and am0+64, k-quad akq;
    //               B thread covers row bkl, n-quad bnq.
    int am0 = tid >> 2, akq = tid & 3;
    int bkl = tid >> 4, bnq = tid & 15;

    // ---- prefetch first tiles ----
    {
        int kk = k0beg;
        va[0] = *(const float4*)(A + (long long)(row0 + am0) * K + kk + akq * 4);
        va[1] = *(const float4*)(A + (long long)(row0 + am0 + 64) * K + kk + akq * 4);
        if (nvec) {
            vb = *(const float4*)(B + (long long)(kk + bkl) * N + col0 + bnq * 4);
        } else {
            const float* bp = B + (long long)(kk + bkl) * N;
            int n0 = col0 + bnq * 4;
            vb.x = (n0 + 0 < N) ? bp[n0 + 0] : 0.f;
            vb.y = (n0 + 1 < N) ? bp[n0 + 1] : 0.f;
            vb.z = (n0 + 2 < N) ? bp[n0 + 2] : 0.f;
            vb.w = (n0 + 3 < N) ? bp[n0 + 3] : 0.f;
        }
    }

    int buf = 0;
    for (int k0 = k0beg; k0 < k0end; k0 += 16) {
        // ---- store staged tiles to canonical smem (tf32) ----
        #pragma unroll
        for (int i = 0; i < 2; i++) {
            int m = am0 + i * 64;
            uint4 u = make_uint4(f2tf32(va[i].x), f2tf32(va[i].y),
                                 f2tf32(va[i].z), f2tf32(va[i].w));
            *(uint4*)&As[buf][m * AS_STRIDE + akq * 4] = u;
        }
        {
            uint4 u = make_uint4(f2tf32(vb.x), f2tf32(vb.y),
                                 f2tf32(vb.z), f2tf32(vb.w));
            *(uint4*)&Bs[buf][bkl * BS_STRIDE + bnq * 4] = u;
        }
        __syncthreads();

        // ---- prefetch next iteration while computing this one ----
        int kn = k0 + 16;
        if (kn < k0end) {
            va[0] = *(const float4*)(A + (long long)(row0 + am0) * K + kn + akq * 4);
            va[1] = *(const float4*)(A + (long long)(row0 + am0 + 64) * K + kn + akq * 4);
            if (nvec) {
                vb = *(const float4*)(B + (long long)(kn + bkl) * N + col0 + bnq * 4);
            } else {
                const float* bp = B + (long long)(kn + bkl) * N;
                int n0 = col0 + bnq * 4;
                vb.x = (n0 + 0 < N) ? bp[n0 + 0] : 0.f;
                vb.y = (n0 + 1 < N) ? bp[n0 + 1] : 0.f;
                vb.z = (n0 + 2 < N) ? bp[n0 + 2] : 0.f;
                vb.w = (n0 + 3 < N) ? bp[n0 + 3] : 0.f;
            }
        }

        // ---- compute: fragment loads from canonical layout (conflict-free) ----
        #pragma unroll
        for (int k8 = 0; k8 < 2; k8++) {
            const uint32_t* as = As[buf];
            const uint32_t* bs = Bs[buf];
            int kb = k8 * 8;
            uint32_t a[2][4];
            #pragma unroll
            for (int mi = 0; mi < 2; mi++) {
                int mb = wm * 32 + mi * 16;
                a[mi][0] = as[(mb + g)     * AS_STRIDE + kb + t];
                a[mi][1] = as[(mb + g + 8) * AS_STRIDE + kb + t];
                a[mi][2] = as[(mb + g)     * AS_STRIDE + kb + t + 4];
                a[mi][3] = as[(mb + g + 8) * AS_STRIDE + kb + t + 4];
            }
            uint32_t b[4][2];
            #pragma unroll
            for (int ni = 0; ni < 4; ni++) {
                int nb = wn * 32 + ni * 8 + g;
                b[ni][0] = bs[(kb + t)     * BS_STRIDE + nb];
                b[ni][1] = bs[(kb + t + 4) * BS_STRIDE + nb];
            }
            #pragma unroll
            for (int mi = 0; mi < 2; mi++)
                #pragma unroll
                for (int ni = 0; ni < 4; ni++)
                    mma_tf32(acc[mi][ni], a[mi], b[ni]);
        }
        buf ^= 1;
    }

    // ---- epilogue ----
    #pragma unroll
    for (int mi = 0; mi < 2; mi++) {
        #pragma unroll
        for (int ni = 0; ni < 4; ni++) {
            int m_base = row0 + wm * 32 + mi * 16 + g;
            int n_base = col0 + wn * 32 + ni * 8 + t * 2;
            #pragma unroll
            for (int r = 0; r < 4; r++) {
                int gm = m_base + ((r >> 1) << 3);
                int gn = n_base + (r & 1);
                if (gn >= N) continue;
                float v = acc[mi][ni][r];
                if (MODE == 0) {
                    if (bias) v += biasScale * bias[gn];
                    C[(long long)gm * N + gn] = v;
                } else {
                    long long br = (long long)(gm >> 5) * biasStride + gn;
                    C [(long long)gm * N + gn] = tanhf(v + bias [br]);
                    C2[(long long)gm * N + gn] = tanhf(v + bias2[br]);
                }
            }
        }
    }
}

__global__ void reduce_add_kernel(const float* __restrict__ src, float* __restrict__ dst,
                                  int parts, long long len)
{
    long long i = (long long)blockIdx.x * 256 + threadIdx.x;
    if (i >= len) return;
    float s = 0.f;
    for (int p = 0; p < parts; p++) s += src[(long long)p * len + i];
    dst[i] = s;
}

// ---------------- stage kernels ----------------
__global__ void rep_kernel(const float* __restrict__ seq, const int* __restrict__ ep)
{
    int bn = blockIdx.x;
    int b = bn / NENT, n = bn % NENT;
    int e0 = ep[(b * NENT + n) * MENT + 0];
    int e1 = ep[(b * NENT + n) * MENT + 1];
    int e2 = ep[(b * NENT + n) * MENT + 2];
    int e3 = ep[(b * NENT + n) * MENT + 3];
    const float* sb = seq + (long long)b * SEQ * HID;
    for (int h = threadIdx.x; h < HID; h += blockDim.x) {
        float v0 = sb[(long long)e0 * HID + h];
        float v1 = sb[(long long)e1 * HID + h];
        float v2 = sb[(long long)e2 * HID + h];
        float v3 = sb[(long long)e3 * HID + h];
        float m = fmaxf(fmaxf(v0, v1), fmaxf(v2, v3));
        float s = expf(v0 - m) + expf(v1 - m) + expf(v2 - m) + expf(v3 - m);
        d_rep[(b * NENT + n) * HID + h] = m + logf(s);
    }
}

__global__ void packA_kernel(const float* __restrict__ A_bl)
{
    int idx = blockIdx.x * 256 + threadIdx.x;
    if (idx >= WD * PP) return;
    int o = idx / PP, pq = idx % PP;
    d_Ablt[pq * WD + o] = A_bl[idx];
}

__global__ void packW_kernel(const float* __restrict__ W_s, const float* __restrict__ W_o)
{
    int idx = blockIdx.x * 256 + threadIdx.x;
    if (idx >= WD * WD) return;
    int k = idx / WD, j = idx % WD;
    d_Wso[(long long)k * (2 * WD) + j]      = W_s[idx];
    d_Wso[(long long)k * (2 * WD) + WD + j] = W_o[idx];
}

__global__ void ga_kernel(const float* __restrict__ att, const int* __restrict__ ep)
{
    int b = blockIdx.z;
    int n = blockIdx.y / HEADS, h = blockIdx.y % HEADS;
    int s = blockIdx.x * blockDim.x + threadIdx.x;
    const float* ab = att + ((long long)(b * HEADS + h)) * SEQ * SEQ;
    float a = 0.f;
    #pragma unroll
    for (int m = 0; m < MENT; m++) {
        int e = ep[(b * NENT + n) * MENT + m];
        a += ab[(long long)e * SEQ + s];
    }
    d_ga[((long long)((b * NENT + n) * HEADS + h)) * SEQ + s] = a;
}

__global__ __launch_bounds__(256) void pa_kernel()
{
    int b = blockIdx.y;
    int ij = blockIdx.x;
    int i = ij >> 5, j = ij & 31;
    const float* gi = d_ga + ((long long)(b * NENT + i)) * HEADS * SEQ;
    const float* gj = d_ga + ((long long)(b * NENT + j)) * HEADS * SEQ;
    int tid = threadIdx.x;
    float acc[4];
    float lsum = 0.f;
    #pragma unroll
    for (int r = 0; r < 4; r++) {
        int s = r * 256 + tid;
        float a = 0.f;
        #pragma unroll
        for (int h = 0; h < HEADS; h++)
            a += gi[h * SEQ + s] * gj[h * SEQ + s];
        acc[r] = a;
        lsum += a;
    }
    __shared__ float red[256];
    red[tid] = lsum;
    __syncthreads();
    for (int off = 128; off > 0; off >>= 1) {
        if (tid < off) red[tid] += red[tid + off];
        __syncthreads();
    }
    float inv = 1.0f / red[0];
    float* po = d_pa + ((long long)(b * NPAIR + ij)) * SEQ;
    #pragma unroll
    for (int r = 0; r < 4; r++)
        po[r * 256 + tid] = acc[r] * inv;
}

__global__ __launch_bounds__(256) void P_kernel()
{
    __shared__ float zs[WD], zo[WD];
    long long row = blockIdx.x;
    for (int w = threadIdx.x; w < WD; w += 256) {
        zs[w] = d_Zs[row * WD + w];
        zo[w] = d_Zo[row * WD + w];
    }
    __syncthreads();
    int t = threadIdx.x;
    if (t < PP) {
        int p = t / DD, q = t % DD;
        float a = 0.f;
        #pragma unroll
        for (int k = 0; k < SPLITK; k++)
            a += zs[p * SPLITK + k] * zo[q * SPLITK + k];
        d_P[row * PP + t] = a;
    }
}

__global__ __launch_bounds__(256) void e_kernel(const float* __restrict__ v_attn)
{
    int row = blockIdx.x;
    int tid = threadIdx.x;
    float val = tanhf(d_t[(long long)row * AD + tid]) * v_attn[tid];
    __shared__ float red[256];
    red[tid] = val;
    __syncthreads();
    for (int off = 128; off > 0; off >>= 1) {
        if (tid < off) red[tid] += red[tid + off];
        __syncthreads();
    }
    if (tid == 0) d_e[row] = red[0];
}

__global__ __launch_bounds__(1024) void softmax_kernel()
{
    int b = blockIdx.x;
    int tid = threadIdx.x;
    int w = tid >> 5, lane = tid & 31;
    const float* eb = d_e + b * NPAIR;
    float v = eb[w * 32 + lane];
    float m = v;
    for (int o = 16; o > 0; o >>= 1) m = fmaxf(m, __shfl_xor_sync(~0u, m, o));
    float ex = expf(v - m);
    float s = ex;
    for (int o = 16; o > 0; o >>= 1) s += __shfl_xor_sync(~0u, s, o);
    d_arow[b * NPAIR + w * 32 + lane] = ex / s;
    float v2 = eb[lane * 32 + w];
    float m2 = v2;
    for (int o = 16; o > 0; o >>= 1) m2 = fmaxf(m2, __shfl_xor_sync(~0u, m2, o));
    float ex2 = expf(v2 - m2);
    float s2 = ex2;
    for (int o = 16; o > 0; o >>= 1) s2 += __shfl_xor_sync(~0u, s2, o);
    d_acol[b * NPAIR + lane * 32 + w] = ex2 / s2;
}

__global__ void rowcolC_kernel()
{
    int b = blockIdx.y, n = blockIdx.x;
    int c = threadIdx.x;
    if (c >= NC) return;
    const float* gc = d_gclf + (long long)b * NPAIR * NC;
    float rs = 0.f, cs = 0.f;
    #pragma unroll 4
    for (int k = 0; k < NENT; k++) {
        rs += d_arow[b * NPAIR + n * 32 + k] * gc[(long long)(n * 32 + k) * NC + c];
        cs += d_acol[b * NPAIR + k * 32 + n] * gc[(long long)(k * 32 + n) * NC + c];
    }
    d_rgcg[(b * NENT + n) * NC + c] = rs;
    d_rgcg[(BATCH * NENT + b * NENT + n) * NC + c] = cs;
}

__global__ void final_kernel(const float* __restrict__ clf_b, float* __restrict__ out)
{
    long long idx = (long long)blockIdx.x * blockDim.x + threadIdx.x;
    const long long total = (long long)BATCH * NPAIR * NC;
    if (idx >= total) return;
    int c = (int)(idx % NC);
    long long rb = idx / NC;
    int ij = (int)(rb % NPAIR);
    int b = (int)(rb / NPAIR);
    int i = ij >> 5, j = ij & 31;
    out[idx] = d_gclf[idx]
             + d_rgcg[(b * NENT + i) * NC + c]
             + d_rgcg[(BATCH * NENT + b * NENT + j) * NC + c]
             + clf_b[c];
}

// ---------------- host launch ----------------
extern "C" void kernel_launch(void* const* d_in, const int* in_sizes, int n_in,
                              void* d_out, int out_size)
{
    const float* seq    = (const float*)d_in[0];
    const float* att    = (const float*)d_in[1];
    const int*   ep     = (const int*)  d_in[2];
    const float* W_s    = (const float*)d_in[3];
    const float* W_o    = (const float*)d_in[4];
    const float* W_c    = (const float*)d_in[5];
    const float* A_bl   = (const float*)d_in[6];
    const float* b_bl   = (const float*)d_in[7];
    const float* W_attn = (const float*)d_in[8];
    const float* v_attn = (const float*)d_in[9];
    const float* clf_W  = (const float*)d_in[10];
    const float* clf_b  = (const float*)d_in[11];
    float* out = (float*)d_out;

    float *p_rep, *p_rso, *p_Wso, *p_pa, *p_ctxh, *p_Zs, *p_Zo, *p_P, *p_Ablt,
          *p_g, *p_t, *p_gclf, *p_part;
    cudaGetSymbolAddress((void**)&p_rep,  d_rep);
    cudaGetSymbolAddress((void**)&p_rso,  d_rso);
    cudaGetSymbolAddress((void**)&p_Wso,  d_Wso);
    cudaGetSymbolAddress((void**)&p_pa,   d_pa);
    cudaGetSymbolAddress((void**)&p_ctxh, d_ctxh);
    cudaGetSymbolAddress((void**)&p_Zs,   d_Zs);
    cudaGetSymbolAddress((void**)&p_Zo,   d_Zo);
    cudaGetSymbolAddress((void**)&p_P,    d_P);
    cudaGetSymbolAddress((void**)&p_Ablt, d_Ablt);
    cudaGetSymbolAddress((void**)&p_g,    d_g);
    cudaGetSymbolAddress((void**)&p_t,    d_t);
    cudaGetSymbolAddress((void**)&p_gclf, d_gclf);
    cudaGetSymbolAddress((void**)&p_part, d_part);

    // 1. entity reps
    rep_kernel<<<BATCH * NENT, 256>>>(seq, ep);
    // 2-3. packs
    packA_kernel<<<(WD * PP + 255) / 256, 256>>>(A_bl);
    packW_kernel<<<(WD * WD + 255) / 256, 256>>>(W_s, W_o);
    // 4. entity attention gather
    {
        dim3 grid(SEQ / 256, NENT * HEADS, BATCH);
        ga_kernel<<<grid, 256>>>(att, ep);
    }
    // 5. pairwise localized attention
    {
        dim3 grid(NPAIR, BATCH);
        pa_kernel<<<grid, 256>>>();
    }
    // 6. ctxh = pa @ seq  (batched)  [1024,768,1024] x4  -> grid 384
    {
        dim3 grid(WD / 64, NPAIR / 128, BATCH);
        mma_gemm<0><<<grid, 256>>>(p_pa, seq, p_ctxh, nullptr,
                                   NPAIR, HID, SEQ,
                                   (long long)NPAIR * SEQ, (long long)SEQ * HID,
                                   (long long)NPAIR * HID,
                                   1, 0, nullptr, 0.f, nullptr, 0);
    }
    // 7. rso partials = rep @ [W_s|W_o]  (split-K 6)  [128,1536,768] -> 144
    {
        dim3 grid((2 * WD) / 64, 1, 6);
        mma_gemm<0><<<grid, 256>>>(p_rep, p_Wso, p_part, nullptr,
                                   BATCH * NENT, 2 * WD, HID, 0, 0, 0,
                                   6, (long long)BATCH * NENT * 2 * WD,
                                   nullptr, 0.f, nullptr, 0);
    }
    // 8. reduce rso
    reduce_add_kernel<<<(BATCH * NENT * 2 * WD + 255) / 256, 256>>>(
        p_part, p_rso, 6, (long long)BATCH * NENT * 2 * WD);
    // 9. fused: Zs/Zo = tanh(rso[i] + ctxh @ W_c)  [4096,768,768] -> 384
    {
        dim3 grid(WD / 64, (BATCH * NPAIR) / 128, 1);
        mma_gemm<1><<<grid, 256>>>(p_ctxh, W_c, p_Zs, p_Zo,
                                   BATCH * NPAIR, WD, HID, 0, 0, 0,
                                   1, 0, p_rso, 0.f, p_rso + WD, 2 * WD);
    }
    // 10. P
    P_kernel<<<BATCH * NPAIR, 256>>>();
    // 11. g = P @ A_bl^T + 64*b_bl  [4096,768,144] -> 384
    {
        dim3 grid(WD / 64, (BATCH * NPAIR) / 128, 1);
        mma_gemm<0><<<grid, 256>>>(p_P, p_Ablt, p_g, nullptr,
                                   BATCH * NPAIR, WD, PP, 0, 0, 0,
                                   1, 0, b_bl, (float)SPLITK, nullptr, 0);
    }
    // 12. t = g @ W_attn  [4096,256,768] -> 128
    {
        dim3 grid(AD / 64, (BATCH * NPAIR) / 128, 1);
        mma_gemm<0><<<grid, 256>>>(p_g, W_attn, p_t, nullptr,
                                   BATCH * NPAIR, AD, WD, 0, 0, 0,
                                   1, 0, nullptr, 0.f, nullptr, 0);
    }
    // 13. e = tanh(t) . v_attn
    e_kernel<<<BATCH * NPAIR, 256>>>(v_attn);
    // 14. softmax
    softmax_kernel<<<BATCH, 1024>>>();
    // 15. gclf partials = g @ clf_W (split-K 4)  [4096,97,768] -> 256
    {
        long long len = (long long)BATCH * NPAIR * NC;
        dim3 grid((NC + 63) / 64, (BATCH * NPAIR) / 128, 4);
        mma_gemm<0><<<grid, 256>>>(p_g, clf_W, p_part, nullptr,
                                   BATCH * NPAIR, NC, WD, 0, 0, 0,
                                   4, len, nullptr, 0.f, nullptr, 0);
        reduce_add_kernel<<<(unsigned)((len + 255) / 256), 256>>>(p_part, p_gclf, 4, len);
    }
    // 16. axis-attention residual folded through clf_W
    {
        dim3 grid(NENT, BATCH);
        rowcolC_kernel<<<grid, 128>>>();
    }
    // 17. out
    {
        long long total = (long long)BATCH * NPAIR * NC;
        final_kernel<<<(unsigned)((total + 255) / 256), 256>>>(clf_b, out);
    }
}

// round 7
// speedup vs baseline: 2.0398x; 1.0093x over previous
#include <cuda_runtime.h>
#include <math.h>
#include <stdint.h>

#define BATCH 4
#define SEQ   1024
#define HID   768
#define HEADS 12
#define NENT  32
#define MENT  4
#define WD    768
#define AD    256
#define NC    97
#define SPLITK 64
#define DD    12
#define PP    144          // DD*DD
#define NPAIR (NENT*NENT)  // 1024

// ---------------- device scratch ----------------
__device__ float d_rep[BATCH*NENT*HID];
__device__ float d_rso[BATCH*NENT*2*WD];          // [128][1536] : rs | ro
__device__ float d_Wso[WD*2*WD];                  // [768][1536] : W_s | W_o
__device__ float d_ga [BATCH*NENT*HEADS*SEQ];
__device__ float d_pa [(size_t)BATCH*NPAIR*SEQ];  // UNNORMALIZED
__device__ float d_painv[BATCH*NPAIR];            // 1 / sum_s pa
__device__ float d_ctxh[(size_t)BATCH*NPAIR*HID];
__device__ float d_Zs [(size_t)BATCH*NPAIR*WD];
__device__ float d_Zo [(size_t)BATCH*NPAIR*WD];
__device__ float d_P  [(size_t)BATCH*NPAIR*PP];
__device__ float d_g  [(size_t)BATCH*NPAIR*WD];
__device__ float d_t  [(size_t)BATCH*NPAIR*AD];
__device__ float d_e  [BATCH*NPAIR];
__device__ float d_arow[BATCH*NPAIR];
__device__ float d_acol[BATCH*NPAIR];
__device__ float d_Ablt[PP*WD];
__device__ float d_gclf[(size_t)BATCH*NPAIR*NC];
__device__ float d_rgcg[2*BATCH*NENT*NC];
__device__ float d_part[1700000];                 // split-K partials

// ---------------- tf32 helpers ----------------
__device__ __forceinline__ uint32_t f2tf32(float x)
{
    uint32_t r;
    asm("cvt.rna.tf32.f32 %0, %1;" : "=r"(r) : "f"(x));
    return r;
}

__device__ __forceinline__ void mma_tf32(float* c, const uint32_t* a, const uint32_t* b)
{
    asm volatile(
        "mma.sync.aligned.m16n8k8.row.col.f32.tf32.tf32.f32 "
        "{%0,%1,%2,%3}, {%4,%5,%6,%7}, {%8,%9}, {%0,%1,%2,%3};"
        : "+f"(c[0]), "+f"(c[1]), "+f"(c[2]), "+f"(c[3])
        : "r"(a[0]), "r"(a[1]), "r"(a[2]), "r"(a[3]), "r"(b[0]), "r"(b[1]));
}

// ---------------- pipelined tf32 tensor-core GEMM (BM=128, BN=64, BK=16) ----------------
// C[M,N] = A[M,K] row * B[K,N] row. 256 thr = 8 warps (4 m-warps x 2 n-warps),
// warp tile 32x32. Canonical padded smem (conflict-free both directions).
// Ping-pong smem + register staging; one sync/iter; tf32 convert at smem store.
// MODE 0: C = acc (+ biasScale*bias[n] if bias).
// MODE 1: C = tanh(acc + bias[(gm>>5)*biasStride+gn]); C2 likewise with bias2.
// MODE 2: C = acc * bias[zb*biasStride + gm]   (per-row scale, batched)
// Requirements: M%128==0, (K/kSplit)%16==0.
#define AS_STRIDE 20
#define BS_STRIDE 72
template<int MODE>
__global__ __launch_bounds__(256)
void mma_gemm(const float* __restrict__ A, const float* __restrict__ B,
              float* __restrict__ C, float* __restrict__ C2,
              int M, int N, int K,
              long long sA, long long sB, long long sC,
              int kSplit, long long partStride,
              const float* __restrict__ bias, float biasScale,
              const float* __restrict__ bias2, int biasStride)
{
    __shared__ uint32_t As[2][128 * AS_STRIDE];   // 2 x 10.0 KB
    __shared__ uint32_t Bs[2][16 * BS_STRIDE];    // 2 x 4.5 KB

    int zb = blockIdx.z / kSplit;
    int kz = blockIdx.z - zb * kSplit;
    A += (long long)zb * sA;
    B += (long long)zb * sB;
    C += (long long)zb * sC + (long long)kz * partStride;

    int row0 = blockIdx.y * 128;
    int col0 = blockIdx.x * 64;
    int tid = threadIdx.x, lane = tid & 31, w = tid >> 5;
    int wm = w & 3, wn = w >> 2;
    int g = lane >> 2, t = lane & 3;

    int kLen = K / kSplit;
    int k0beg = kz * kLen, k0end = k0beg + kLen;

    float acc[2][4][4];
    #pragma unroll
    for (int i = 0; i < 2; i++)
        #pragma unroll
        for (int j = 0; j < 4; j++)
            #pragma unroll
            for (int r = 0; r < 4; r++) acc[i][j][r] = 0.f;

    const bool nvec = ((N & 3) == 0);

    float4 va[2], vb;

    int am0 = tid >> 2, akq = tid & 3;
    int bkl = tid >> 4, bnq = tid & 15;

    // ---- prefetch first tiles ----
    {
        int kk = k0beg;
        va[0] = *(const float4*)(A + (long long)(row0 + am0) * K + kk + akq * 4);
        va[1] = *(const float4*)(A + (long long)(row0 + am0 + 64) * K + kk + akq * 4);
        if (nvec) {
            vb = *(const float4*)(B + (long long)(kk + bkl) * N + col0 + bnq * 4);
        } else {
            const float* bp = B + (long long)(kk + bkl) * N;
            int n0 = col0 + bnq * 4;
            vb.x = (n0 + 0 < N) ? bp[n0 + 0] : 0.f;
            vb.y = (n0 + 1 < N) ? bp[n0 + 1] : 0.f;
            vb.z = (n0 + 2 < N) ? bp[n0 + 2] : 0.f;
            vb.w = (n0 + 3 < N) ? bp[n0 + 3] : 0.f;
        }
    }

    int buf = 0;
    for (int k0 = k0beg; k0 < k0end; k0 += 16) {
        #pragma unroll
        for (int i = 0; i < 2; i++) {
            int m = am0 + i * 64;
            uint4 u = make_uint4(f2tf32(va[i].x), f2tf32(va[i].y),
                                 f2tf32(va[i].z), f2tf32(va[i].w));
            *(uint4*)&As[buf][m * AS_STRIDE + akq * 4] = u;
        }
        {
            uint4 u = make_uint4(f2tf32(vb.x), f2tf32(vb.y),
                                 f2tf32(vb.z), f2tf32(vb.w));
            *(uint4*)&Bs[buf][bkl * BS_STRIDE + bnq * 4] = u;
        }
        __syncthreads();

        int kn = k0 + 16;
        if (kn < k0end) {
            va[0] = *(const float4*)(A + (long long)(row0 + am0) * K + kn + akq * 4);
            va[1] = *(const float4*)(A + (long long)(row0 + am0 + 64) * K + kn + akq * 4);
            if (nvec) {
                vb = *(const float4*)(B + (long long)(kn + bkl) * N + col0 + bnq * 4);
            } else {
                const float* bp = B + (long long)(kn + bkl) * N;
                int n0 = col0 + bnq * 4;
                vb.x = (n0 + 0 < N) ? bp[n0 + 0] : 0.f;
                vb.y = (n0 + 1 < N) ? bp[n0 + 1] : 0.f;
                vb.z = (n0 + 2 < N) ? bp[n0 + 2] : 0.f;
                vb.w = (n0 + 3 < N) ? bp[n0 + 3] : 0.f;
            }
        }

        #pragma unroll
        for (int k8 = 0; k8 < 2; k8++) {
            const uint32_t* as = As[buf];
            const uint32_t* bs = Bs[buf];
            int kb = k8 * 8;
            uint32_t a[2][4];
            #pragma unroll
            for (int mi = 0; mi < 2; mi++) {
                int mb = wm * 32 + mi * 16;
                a[mi][0] = as[(mb + g)     * AS_STRIDE + kb + t];
                a[mi][1] = as[(mb + g + 8) * AS_STRIDE + kb + t];
                a[mi][2] = as[(mb + g)     * AS_STRIDE + kb + t + 4];
                a[mi][3] = as[(mb + g + 8) * AS_STRIDE + kb + t + 4];
            }
            uint32_t b[4][2];
            #pragma unroll
            for (int ni = 0; ni < 4; ni++) {
                int nb = wn * 32 + ni * 8 + g;
                b[ni][0] = bs[(kb + t)     * BS_STRIDE + nb];
                b[ni][1] = bs[(kb + t + 4) * BS_STRIDE + nb];
            }
            #pragma unroll
            for (int mi = 0; mi < 2; mi++)
                #pragma unroll
                for (int ni = 0; ni < 4; ni++)
                    mma_tf32(acc[mi][ni], a[mi], b[ni]);
        }
        buf ^= 1;
    }

    // ---- epilogue ----
    #pragma unroll
    for (int mi = 0; mi < 2; mi++) {
        #pragma unroll
        for (int ni = 0; ni < 4; ni++) {
            int m_base = row0 + wm * 32 + mi * 16 + g;
            int n_base = col0 + wn * 32 + ni * 8 + t * 2;
            #pragma unroll
            for (int r = 0; r < 4; r++) {
                int gm = m_base + ((r >> 1) << 3);
                int gn = n_base + (r & 1);
                if (gn >= N) continue;
                float v = acc[mi][ni][r];
                if (MODE == 0) {
                    if (bias) v += biasScale * bias[gn];
                    C[(long long)gm * N + gn] = v;
                } else if (MODE == 1) {
                    long long br = (long long)(gm >> 5) * biasStride + gn;
                    C [(long long)gm * N + gn] = tanhf(v + bias [br]);
                    C2[(long long)gm * N + gn] = tanhf(v + bias2[br]);
                } else {
                    v *= bias[(long long)zb * biasStride + gm];
                    C[(long long)gm * N + gn] = v;
                }
            }
        }
    }
}

__global__ void reduce_add_kernel(const float* __restrict__ src, float* __restrict__ dst,
                                  int parts, long long len)
{
    long long i = (long long)blockIdx.x * 256 + threadIdx.x;
    if (i >= len) return;
    float s = 0.f;
    for (int p = 0; p < parts; p++) s += src[(long long)p * len + i];
    dst[i] = s;
}

// ---------------- stage kernels ----------------
__global__ void rep_kernel(const float* __restrict__ seq, const int* __restrict__ ep)
{
    int bn = blockIdx.x;
    int b = bn / NENT, n = bn % NENT;
    int e0 = ep[(b * NENT + n) * MENT + 0];
    int e1 = ep[(b * NENT + n) * MENT + 1];
    int e2 = ep[(b * NENT + n) * MENT + 2];
    int e3 = ep[(b * NENT + n) * MENT + 3];
    const float* sb = seq + (long long)b * SEQ * HID;
    for (int h = threadIdx.x; h < HID; h += blockDim.x) {
        float v0 = sb[(long long)e0 * HID + h];
        float v1 = sb[(long long)e1 * HID + h];
        float v2 = sb[(long long)e2 * HID + h];
        float v3 = sb[(long long)e3 * HID + h];
        float m = fmaxf(fmaxf(v0, v1), fmaxf(v2, v3));
        float s = expf(v0 - m) + expf(v1 - m) + expf(v2 - m) + expf(v3 - m);
        d_rep[(b * NENT + n) * HID + h] = m + logf(s);
    }
}

__global__ void packA_kernel(const float* __restrict__ A_bl)
{
    int idx = blockIdx.x * 256 + threadIdx.x;
    if (idx >= WD * PP) return;
    int o = idx / PP, pq = idx % PP;
    d_Ablt[pq * WD + o] = A_bl[idx];
}

__global__ void packW_kernel(const float* __restrict__ W_s, const float* __restrict__ W_o)
{
    int idx = blockIdx.x * 256 + threadIdx.x;
    if (idx >= WD * WD) return;
    int k = idx / WD, j = idx % WD;
    d_Wso[(long long)k * (2 * WD) + j]      = W_s[idx];
    d_Wso[(long long)k * (2 * WD) + WD + j] = W_o[idx];
}

__global__ void ga_kernel(const float* __restrict__ att, const int* __restrict__ ep)
{
    int b = blockIdx.z;
    int n = blockIdx.y / HEADS, h = blockIdx.y % HEADS;
    int s = blockIdx.x * blockDim.x + threadIdx.x;
    const float* ab = att + ((long long)(b * HEADS + h)) * SEQ * SEQ;
    float a = 0.f;
    #pragma unroll
    for (int m = 0; m < MENT; m++) {
        int e = ep[(b * NENT + n) * MENT + m];
        a += ab[(long long)e * SEQ + s];
    }
    d_ga[((long long)((b * NENT + n) * HEADS + h)) * SEQ + s] = a;
}

// Pair-tiled pa: block = (tj, ti, b) handles 4 i x 4 j pairs.
// Stages ga chunks for the 8 entities in dynamic smem (96KB), computes
// unnormalized pa and per-pair reciprocal sums. 24KB L2 traffic per pair
// (vs 96KB in the per-pair version).
__global__ __launch_bounds__(256) void pa_tiled_kernel()
{
    extern __shared__ float sm[];          // [0:12288) gi, [12288:24576) gj
    __shared__ float sred[16 * 8];
    int b = blockIdx.z, ti = blockIdx.y, tj = blockIdx.x;
    int tid = threadIdx.x, lane = tid & 31, w = tid >> 5;

    float psum[16];
    #pragma unroll
    for (int p = 0; p < 16; p++) psum[p] = 0.f;

    for (int c = 0; c < 4; c++) {
        int s0 = c * 256;
        // load 4 i-entities and 4 j-entities: 12 heads x 256 s each
        for (int l = tid; l < 3072; l += 256) {
            int il = l / 768;
            int rem = l - il * 768;
            int h = rem / 64, sq = rem - h * 64;
            int smoff = (il * 12 + h) * 256 + sq * 4;
            *(float4*)&sm[smoff] =
                *(const float4*)&d_ga[(((long long)(b * NENT + ti * 4 + il) * HEADS + h) << 10) + s0 + sq * 4];
            *(float4*)&sm[12288 + smoff] =
                *(const float4*)&d_ga[(((long long)(b * NENT + tj * 4 + il) * HEADS + h) << 10) + s0 + sq * 4];
        }
        __syncthreads();

        float acc[16];
        #pragma unroll
        for (int p = 0; p < 16; p++) acc[p] = 0.f;
        #pragma unroll
        for (int h = 0; h < HEADS; h++) {
            float ai[4], bj[4];
            #pragma unroll
            for (int il = 0; il < 4; il++) ai[il] = sm[(il * 12 + h) * 256 + tid];
            #pragma unroll
            for (int jl = 0; jl < 4; jl++) bj[jl] = sm[12288 + (jl * 12 + h) * 256 + tid];
            #pragma unroll
            for (int il = 0; il < 4; il++)
                #pragma unroll
                for (int jl = 0; jl < 4; jl++)
                    acc[il * 4 + jl] += ai[il] * bj[jl];
        }
        #pragma unroll
        for (int il = 0; il < 4; il++)
            #pragma unroll
            for (int jl = 0; jl < 4; jl++) {
                int p = il * 4 + jl;
                int ij = (ti * 4 + il) * NENT + tj * 4 + jl;
                d_pa[((long long)(b * NPAIR + ij) << 10) + s0 + tid] = acc[p];
                psum[p] += acc[p];
            }
        __syncthreads();
    }

    // block-reduce the 16 pair sums
    #pragma unroll
    for (int p = 0; p < 16; p++) {
        #pragma unroll
        for (int o = 16; o > 0; o >>= 1)
            psum[p] += __shfl_xor_sync(~0u, psum[p], o);
    }
    if (lane == 0)
        #pragma unroll
        for (int p = 0; p < 16; p++) sred[p * 8 + w] = psum[p];
    __syncthreads();
    if (tid < 16) {
        float s = 0.f;
        #pragma unroll
        for (int ww = 0; ww < 8; ww++) s += sred[tid * 8 + ww];
        int il = tid >> 2, jl = tid & 3;
        int ij = (ti * 4 + il) * NENT + tj * 4 + jl;
        d_painv[b * NPAIR + ij] = 1.0f / s;
    }
}

__global__ __launch_bounds__(256) void P_kernel()
{
    __shared__ float zs[WD], zo[WD];
    long long row = blockIdx.x;
    for (int w = threadIdx.x; w < WD; w += 256) {
        zs[w] = d_Zs[row * WD + w];
        zo[w] = d_Zo[row * WD + w];
    }
    __syncthreads();
    int t = threadIdx.x;
    if (t < PP) {
        int p = t / DD, q = t % DD;
        float a = 0.f;
        #pragma unroll
        for (int k = 0; k < SPLITK; k++)
            a += zs[p * SPLITK + k] * zo[q * SPLITK + k];
        d_P[row * PP + t] = a;
    }
}

__global__ __launch_bounds__(256) void e_kernel(const float* __restrict__ v_attn)
{
    int row = blockIdx.x;
    int tid = threadIdx.x;
    float val = tanhf(d_t[(long long)row * AD + tid]) * v_attn[tid];
    __shared__ float red[256];
    red[tid] = val;
    __syncthreads();
    for (int off = 128; off > 0; off >>= 1) {
        if (tid < off) red[tid] += red[tid + off];
        __syncthreads();
    }
    if (tid == 0) d_e[row] = red[0];
}

__global__ __launch_bounds__(1024) void softmax_kernel()
{
    int b = blockIdx.x;
    int tid = threadIdx.x;
    int w = tid >> 5, lane = tid & 31;
    const float* eb = d_e + b * NPAIR;
    float v = eb[w * 32 + lane];
    float m = v;
    for (int o = 16; o > 0; o >>= 1) m = fmaxf(m, __shfl_xor_sync(~0u, m, o));
    float ex = expf(v - m);
    float s = ex;
    for (int o = 16; o > 0; o >>= 1) s += __shfl_xor_sync(~0u, s, o);
    d_arow[b * NPAIR + w * 32 + lane] = ex / s;
    float v2 = eb[lane * 32 + w];
    float m2 = v2;
    for (int o = 16; o > 0; o >>= 1) m2 = fmaxf(m2, __shfl_xor_sync(~0u, m2, o));
    float ex2 = expf(v2 - m2);
    float s2 = ex2;
    for (int o = 16; o > 0; o >>= 1) s2 += __shfl_xor_sync(~0u, s2, o);
    d_acol[b * NPAIR + lane * 32 + w] = ex2 / s2;
}

__global__ void rowcolC_kernel()
{
    int b = blockIdx.y, n = blockIdx.x;
    int c = threadIdx.x;
    if (c >= NC) return;
    const float* gc = d_gclf + (long long)b * NPAIR * NC;
    float rs = 0.f, cs = 0.f;
    #pragma unroll 4
    for (int k = 0; k < NENT; k++) {
        rs += d_arow[b * NPAIR + n * 32 + k] * gc[(long long)(n * 32 + k) * NC + c];
        cs += d_acol[b * NPAIR + k * 32 + n] * gc[(long long)(k * 32 + n) * NC + c];
    }
    d_rgcg[(b * NENT + n) * NC + c] = rs;
    d_rgcg[(BATCH * NENT + b * NENT + n) * NC + c] = cs;
}

__global__ void final_kernel(const float* __restrict__ clf_b, float* __restrict__ out)
{
    long long idx = (long long)blockIdx.x * blockDim.x + threadIdx.x;
    const long long total = (long long)BATCH * NPAIR * NC;
    if (idx >= total) return;
    int c = (int)(idx % NC);
    long long rb = idx / NC;
    int ij = (int)(rb % NPAIR);
    int b = (int)(rb / NPAIR);
    int i = ij >> 5, j = ij & 31;
    out[idx] = d_gclf[idx]
             + d_rgcg[(b * NENT + i) * NC + c]
             + d_rgcg[(BATCH * NENT + b * NENT + j) * NC + c]
             + clf_b[c];
}

// ---------------- host launch ----------------
extern "C" void kernel_launch(void* const* d_in, const int* in_sizes, int n_in,
                              void* d_out, int out_size)
{
    const float* seq    = (const float*)d_in[0];
    const float* att    = (const float*)d_in[1];
    const int*   ep     = (const int*)  d_in[2];
    const float* W_s    = (const float*)d_in[3];
    const float* W_o    = (const float*)d_in[4];
    const float* W_c    = (const float*)d_in[5];
    const float* A_bl   = (const float*)d_in[6];
    const float* b_bl   = (const float*)d_in[7];
    const float* W_attn = (const float*)d_in[8];
    const float* v_attn = (const float*)d_in[9];
    const float* clf_W  = (const float*)d_in[10];
    const float* clf_b  = (const float*)d_in[11];
    float* out = (float*)d_out;

    float *p_rep, *p_rso, *p_Wso, *p_pa, *p_painv, *p_ctxh, *p_Zs, *p_Zo, *p_P,
          *p_Ablt, *p_g, *p_t, *p_gclf, *p_part;
    cudaGetSymbolAddress((void**)&p_rep,   d_rep);
    cudaGetSymbolAddress((void**)&p_rso,   d_rso);
    cudaGetSymbolAddress((void**)&p_Wso,   d_Wso);
    cudaGetSymbolAddress((void**)&p_pa,    d_pa);
    cudaGetSymbolAddress((void**)&p_painv, d_painv);
    cudaGetSymbolAddress((void**)&p_ctxh,  d_ctxh);
    cudaGetSymbolAddress((void**)&p_Zs,    d_Zs);
    cudaGetSymbolAddress((void**)&p_Zo,    d_Zo);
    cudaGetSymbolAddress((void**)&p_P,     d_P);
    cudaGetSymbolAddress((void**)&p_Ablt,  d_Ablt);
    cudaGetSymbolAddress((void**)&p_g,     d_g);
    cudaGetSymbolAddress((void**)&p_t,     d_t);
    cudaGetSymbolAddress((void**)&p_gclf,  d_gclf);
    cudaGetSymbolAddress((void**)&p_part,  d_part);

    static bool attrSet = false;
    if (!attrSet) {
        cudaFuncSetAttribute(pa_tiled_kernel,
                             cudaFuncAttributeMaxDynamicSharedMemorySize, 98304);
        attrSet = true;
    }

    // 0. entity attention gather
    {
        dim3 grid(SEQ / 256, NENT * HEADS, BATCH);
        ga_kernel<<<grid, 256>>>(att, ep);
    }
    // 1. pairwise localized attention (unnormalized + reciprocal sums)
    {
        dim3 grid(8, 8, BATCH);
        pa_tiled_kernel<<<grid, 256, 98304>>>();
    }
    // 2. entity reps
    rep_kernel<<<BATCH * NENT, 256>>>(seq, ep);
    // 3. ctxh = (pa @ seq) * painv[row]  (batched)  [1024,768,1024] x4 -> grid 384
    {
        dim3 grid(WD / 64, NPAIR / 128, BATCH);
        mma_gemm<2><<<grid, 256>>>(p_pa, seq, p_ctxh, nullptr,
                                   NPAIR, HID, SEQ,
                                   (long long)NPAIR * SEQ, (long long)SEQ * HID,
                                   (long long)NPAIR * HID,
                                   1, 0, p_painv, 0.f, nullptr, NPAIR);
    }
    // 4-5. packs
    packA_kernel<<<(WD * PP + 255) / 256, 256>>>(A_bl);
    packW_kernel<<<(WD * WD + 255) / 256, 256>>>(W_s, W_o);
    // 6. rso partials = rep @ [W_s|W_o]  (split-K 6)  [128,1536,768] -> 144
    {
        dim3 grid((2 * WD) / 64, 1, 6);
        mma_gemm<0><<<grid, 256>>>(p_rep, p_Wso, p_part, nullptr,
                                   BATCH * NENT, 2 * WD, HID, 0, 0, 0,
                                   6, (long long)BATCH * NENT * 2 * WD,
                                   nullptr, 0.f, nullptr, 0);
    }
    // 7. reduce rso
    reduce_add_kernel<<<(BATCH * NENT * 2 * WD + 255) / 256, 256>>>(
        p_part, p_rso, 6, (long long)BATCH * NENT * 2 * WD);
    // 8. fused: Zs/Zo = tanh(rso[i] + ctxh @ W_c)  [4096,768,768] -> 384
    {
        dim3 grid(WD / 64, (BATCH * NPAIR) / 128, 1);
        mma_gemm<1><<<grid, 256>>>(p_ctxh, W_c, p_Zs, p_Zo,
                                   BATCH * NPAIR, WD, HID, 0, 0, 0,
                                   1, 0, p_rso, 0.f, p_rso + WD, 2 * WD);
    }
    // 9. P
    P_kernel<<<BATCH * NPAIR, 256>>>();
    // 10. g = P @ A_bl^T + 64*b_bl  [4096,768,144] -> 384
    {
        dim3 grid(WD / 64, (BATCH * NPAIR) / 128, 1);
        mma_gemm<0><<<grid, 256>>>(p_P, p_Ablt, p_g, nullptr,
                                   BATCH * NPAIR, WD, PP, 0, 0, 0,
                                   1, 0, b_bl, (float)SPLITK, nullptr, 0);
    }
    // 11. t = g @ W_attn  [4096,256,768] -> 128
    {
        dim3 grid(AD / 64, (BATCH * NPAIR) / 128, 1);
        mma_gemm<0><<<grid, 256>>>(p_g, W_attn, p_t, nullptr,
                                   BATCH * NPAIR, AD, WD, 0, 0, 0,
                                   1, 0, nullptr, 0.f, nullptr, 0);
    }
    // 12. e = tanh(t) . v_attn
    e_kernel<<<BATCH * NPAIR, 256>>>(v_attn);
    // 13. softmax
    softmax_kernel<<<BATCH, 1024>>>();
    // 14. gclf partials = g @ clf_W (split-K 4)  [4096,97,768] -> 256
    {
        long long len = (long long)BATCH * NPAIR * NC;
        dim3 grid((NC + 63) / 64, (BATCH * NPAIR) / 128, 4);
        mma_gemm<0><<<grid, 256>>>(p_g, clf_W, p_part, nullptr,
                                   BATCH * NPAIR, NC, WD, 0, 0, 0,
                                   4, len, nullptr, 0.f, nullptr, 0);
        reduce_add_kernel<<<(unsigned)((len + 255) / 256), 256>>>(p_part, p_gclf, 4, len);
    }
    // 15. axis-attention residual folded through clf_W
    {
        dim3 grid(NENT, BATCH);
        rowcolC_kernel<<<grid, 128>>>();
    }
    // 16. out
    {
        long long total = (long long)BATCH * NPAIR * NC;
        final_kernel<<<(unsigned)((total + 255) / 256), 256>>>(clf_b, out);
    }
}